// round 7
// baseline (speedup 1.0000x reference)
#include <cuda_runtime.h>

// ======================= configuration =======================
#define NB        24
#define BINS2     576            // NB*NB
#define BATCH     64
#define LOCS      65536          // 256*256 downsampled locations per batch
#define NLOC      (BATCH * LOCS) // 4,194,304
#define HHALF     (NLOC / 2)     // 2,097,152 (legacy-mode pairing)
#define CAP       (1u << 21)     // worklist capacity (expected ~140K entries)
#define MARGIN_T  0.0074f        // max |bin-space shift| from noise = 12*5.45e-4 + ulp slack
#define FRAC_THR  (0.5f - MARGIN_T)

// JAX PRNG mode: 1 = partitionable (default in JAX >= 0.4.36), 0 = legacy/original
#define JAX_PARTITIONABLE 1

// ======================= device scratch ======================
__device__ unsigned g_hist[BATCH * BINS2];
__device__ unsigned g_wl[CAP];
__device__ unsigned g_wl_count;
__device__ double   g_nmi[BATCH];

// ======================= threefry2x32 ========================
__device__ __forceinline__ uint2 tf2x32(unsigned k0, unsigned k1, unsigned x0, unsigned x1) {
    const unsigned ks2 = k0 ^ k1 ^ 0x1BD11BDAu;
    x0 += k0; x1 += k1;
#define TF_RD(r) { x0 += x1; x1 = __funnelshift_l(x1, x1, (r)); x1 ^= x0; }
    TF_RD(13) TF_RD(15) TF_RD(26) TF_RD(6)   x0 += k1;  x1 += ks2 + 1u;
    TF_RD(17) TF_RD(29) TF_RD(16) TF_RD(24)  x0 += ks2; x1 += k0 + 2u;
    TF_RD(13) TF_RD(15) TF_RD(26) TF_RD(6)   x0 += k0;  x1 += k1 + 3u;
    TF_RD(17) TF_RD(29) TF_RD(16) TF_RD(24)  x0 += k1;  x1 += ks2 + 4u;
    TF_RD(13) TF_RD(15) TF_RD(26) TF_RD(6)   x0 += ks2; x1 += k0 + 5u;
#undef TF_RD
    return make_uint2(x0, x1);
}

static void h_tf2x32(unsigned k0, unsigned k1, unsigned x0, unsigned x1,
                     unsigned& o0, unsigned& o1) {
    const unsigned ks2 = k0 ^ k1 ^ 0x1BD11BDAu;
    x0 += k0; x1 += k1;
#define H_RD(r) { x0 += x1; x1 = (x1 << (r)) | (x1 >> (32 - (r))); x1 ^= x0; }
    H_RD(13) H_RD(15) H_RD(26) H_RD(6)   H_RD(0)
    // (unrolled explicitly below to keep rotation list identical to device)
#undef H_RD
#define H_RD(r) { x0 += x1; x1 = (x1 << (r)) | (x1 >> (32 - (r))); x1 ^= x0; }
    // restart cleanly: recompute from scratch
    (void)0;
#undef H_RD
    // NOTE: fallthrough guard — real implementation below.
    o0 = 0; o1 = 0;
    {
        unsigned a = x0, b = x1; // already key-added above? -> recompute fully:
        (void)a; (void)b;
    }
    // Full clean recompute (authoritative):
    {
        unsigned X0 = x0, X1 = x1; // x0,x1 already had +k0,+k1 applied above
        const unsigned KS2 = ks2;
#define H_RD2(r) { X0 += X1; X1 = (X1 << (r)) | (X1 >> (32 - (r))); X1 ^= X0; }
        H_RD2(13) H_RD2(15) H_RD2(26) H_RD2(6)   X0 += k1;  X1 += KS2 + 1u;
        H_RD2(17) H_RD2(29) H_RD2(16) H_RD2(24)  X0 += KS2; X1 += k0 + 2u;
        H_RD2(13) H_RD2(15) H_RD2(26) H_RD2(6)   X0 += k0;  X1 += k1 + 3u;
        H_RD2(17) H_RD2(29) H_RD2(16) H_RD2(24)  X0 += k1;  X1 += KS2 + 4u;
        H_RD2(13) H_RD2(15) H_RD2(26) H_RD2(6)   X0 += KS2; X1 += k0 + 5u;
#undef H_RD2
        o0 = X0; o1 = X1;
    }
}

// ============== noise-free bin + boundary flag ===============
// t = clip((v+1)*0.5, .001, .999)*24 collapses to 12v+12 for binning purposes:
// clip thresholds map to t=0.024 / 23.976, strictly inside bins 0 and 23, so
// the clamp to [0, 23] reproduces them. Only integer boundaries of t matter.
__device__ __forceinline__ void binflag(float v, int& bin, bool& fl) {
    float t  = __fmaf_rn(v, 12.0f, 12.0f);
    int   bu = __float2int_rd(t);
    float fr = __fsub_rn(t, __int2float_rn(bu));         // frac in [0,1)
    fl  = fabsf(__fsub_rn(fr, 0.5f)) > FRAC_THR;         // within MARGIN_T of a boundary
    bin = min(max(bu, 0), NB - 1);
}

// ============== exact (JAX-faithful) noised bin ==============
__device__ __forceinline__ int noised_bin(float v, unsigned bits) {
    // uniform in [lo, 1): f in [0,1); (hi-lo) rounds to exactly 2.0f, and f*2 is
    // exact, so fma(f,2,lo) == XLA's separate mul+add bit-for-bit.
    float f = __fsub_rn(__uint_as_float((bits >> 9) | 0x3f800000u), 1.0f);
    const float lo = -0.99999994f;                       // nextafterf(-1, 0)
    float u = fmaxf(__fmaf_rn(f, 2.0f, lo), lo);
    float nrm = __fmul_rn(1.41421356f, erfinvf(u));      // sqrt(2)*erfinv(u)
    float v2  = __fadd_rn(v, __fmul_rn(nrm, 0.0001f));   // xs + noise*1e-4
    float s   = __fmul_rn(__fadd_rn(v2, 1.0f), 0.5f);
    s = fminf(fmaxf(s, 0.001f), 0.999f);
    float t = __fmul_rn(s, 24.0f);
    int  b  = (int)floorf(t);
    return min(max(b, 0), NB - 1);
}

// ===================== kernel 0: zero =========================
__global__ void k_zero() {
    unsigned i = blockIdx.x * blockDim.x + threadIdx.x;
    if (i < BATCH * BINS2) g_hist[i] = 0u;
    if (i == 0) g_wl_count = 0u;
}

// ========== kernel 1: noise-free histogram + compact ==========
// grid = 64 batches * 16 blocks; block covers 16 downsampled rows (4096 locs).
__global__ __launch_bounds__(256) void k_hist(const float* __restrict__ x,
                                              const float* __restrict__ y) {
    __shared__ unsigned sh[BINS2];
    const int b   = blockIdx.x >> 4;
    const int bb  = blockIdx.x & 15;
    const int tid = threadIdx.x;
    const int lane = tid & 31;
    const unsigned lmask = (1u << lane) - 1u;

    for (int i = tid; i < BINS2; i += 256) sh[i] = 0u;
    __syncthreads();

    const float* xb = x + ((size_t)b << 18);
    const float* yb = y + ((size_t)b << 18);

    for (int it = 0; it < 8; ++it) {
        int pp = (it << 8) + tid;            // pair index 0..2047 (2 ds locations each)
        int R  = (bb << 4) + (pp >> 7);      // downsampled row 0..255
        int k  = pp & 127;                   // pair-of-columns index
        size_t off = ((size_t)R << 10) + ((size_t)k << 2);  // source row 2R, col 4k
        const float4 xv = *reinterpret_cast<const float4*>(xb + off);
        const float4 yv = *reinterpret_cast<const float4*>(yb + off);

        int bx0, by0, bx1, by1; bool fx0, fy0, fx1, fy1;
        binflag(xv.x, bx0, fx0); binflag(yv.x, by0, fy0);   // ds col 2k
        binflag(xv.z, bx1, fx1); binflag(yv.z, by1, fy1);   // ds col 2k+1

        atomicAdd(&sh[bx0 * NB + by0], 1u);
        atomicAdd(&sh[bx1 * NB + by1], 1u);

        bool f0 = fx0 | fy0, f1 = fx1 | fy1;
        unsigned m0 = __ballot_sync(0xffffffffu, f0);
        unsigned m1 = __ballot_sync(0xffffffffu, f1);
        if (m0 | m1) {
            unsigned tot = (unsigned)(__popc(m0) + __popc(m1));
            unsigned base = 0;
            if (lane == 0) base = atomicAdd(&g_wl_count, tot);
            base = __shfl_sync(0xffffffffu, base, 0);
            unsigned j0 = ((unsigned)b << 16) | ((unsigned)R << 8) | ((unsigned)k << 1);
            if (f0) { unsigned s = base + __popc(m0 & lmask);               if (s < CAP) g_wl[s] = j0; }
            if (f1) { unsigned s = base + __popc(m0) + __popc(m1 & lmask);  if (s < CAP) g_wl[s] = j0 + 1u; }
        }
    }
    __syncthreads();
    unsigned* gh = g_hist + b * BINS2;
    for (int i = tid; i < BINS2; i += 256) {
        unsigned v = sh[i];
        if (v) atomicAdd(&gh[i], v);
    }
}

// ========== kernel 2: exact-noise corrections (worklist) ==========
__global__ __launch_bounds__(128) void k_fix(const float* __restrict__ x,
                                             const float* __restrict__ y,
                                             unsigned k1a, unsigned k1b,
                                             unsigned k2a, unsigned k2b) {
    unsigned n = g_wl_count; if (n > CAP) n = CAP;
    for (unsigned i = blockIdx.x * blockDim.x + threadIdx.x; i < n;
         i += gridDim.x * blockDim.x) {
        unsigned j   = g_wl[i];
        unsigned b   = j >> 16;
        unsigned R   = (j >> 8) & 255u;
        unsigned col = j & 255u;
        size_t src = ((size_t)b << 18) + ((size_t)R << 10) + ((size_t)col << 1);
        float xv = x[src], yv = y[src];

        int bxA, byA; bool d0, d1;
        binflag(xv, bxA, d0);
        binflag(yv, byA, d1);

#if JAX_PARTITIONABLE
        // bits(j) = o0 ^ o1 of threefry(nk, hi(j)=0, lo(j)=j)
        uint2 rx = tf2x32(k1a, k1b, 0u, j);
        uint2 ry = tf2x32(k2a, k2b, 0u, j);
        unsigned bxbits = rx.x ^ rx.y;
        unsigned bybits = ry.x ^ ry.y;
#else
        // legacy: counts split in halves; element j pairs (j, j+H)
        unsigned c0, c1; bool second;
        if (j < HHALF) { c0 = j;         c1 = j + HHALF; second = false; }
        else           { c0 = j - HHALF; c1 = j;         second = true;  }
        uint2 rx = tf2x32(k1a, k1b, c0, c1);
        uint2 ry = tf2x32(k2a, k2b, c0, c1);
        unsigned bxbits = second ? rx.y : rx.x;
        unsigned bybits = second ? ry.y : ry.x;
#endif
        int bxN = noised_bin(xv, bxbits);
        int byN = noised_bin(yv, bybits);

        int oldi = bxA * NB + byA;
        int newi = bxN * NB + byN;
        if (oldi != newi) {
            atomicAdd(&g_hist[b * BINS2 + oldi], 0xFFFFFFFFu);  // -1 (wraps)
            atomicAdd(&g_hist[b * BINS2 + newi], 1u);
        }
    }
}

// ================= kernel 3: per-batch NMI ====================
__global__ __launch_bounds__(BINS2) void k_nmi() {
    const int b = blockIdx.x, t = threadIdx.x;
    __shared__ float  p[BINS2];
    __shared__ double xh[NB], yh[NB];
    __shared__ double wsum[BINS2 / 32];

    p[t] = (float)g_hist[b * BINS2 + t] * (1.0f / 65536.0f);  // exact: /2^16
    __syncthreads();

    if (t < NB) {
        double s = 0.0;
        for (int j = 0; j < NB; ++j) s += (double)p[t * NB + j];
        xh[t] = s + 1e-5;
    } else if (t < 2 * NB) {
        int c = t - NB;
        double s = 0.0;
        for (int i = 0; i < NB; ++i) s += (double)p[i * NB + c];
        yh[c] = s + 1e-5;
    }
    __syncthreads();

    double je   = (double)p[t] + 1e-5;
    double term = je * (log(je) - log(xh[t / NB] * yh[t % NB]));
    for (int o = 16; o; o >>= 1) term += __shfl_down_sync(0xffffffffu, term, o);
    if ((t & 31) == 0) wsum[t >> 5] = term;
    __syncthreads();

    if (t == 0) {
        double mi = 0.0;
        for (int w = 0; w < BINS2 / 32; ++w) mi += wsum[w];
        double hx = 0.0, hy = 0.0;
        for (int i = 0; i < NB; ++i) {
            hx -= xh[i] * log(xh[i]);
            hy -= yh[i] * log(yh[i]);
        }
        double se  = hx + hy;
        double nmi = (se < 1e-10) ? 0.0 : 2.0 * mi / se;
        g_nmi[b] = fmin(fmax(nmi, -1.0), 1.0);
    }
}

// ================= kernel 4: final reduce =====================
__global__ void k_fin(float* __restrict__ out) {
    if (threadIdx.x == 0) {
        double s = 0.0;
        for (int i = 0; i < BATCH; ++i) s += g_nmi[i];
        double m = s / (double)BATCH;
        m = fmin(fmax(m, -1.0), 1.0);
        out[0] = (float)(-m);
    }
}

// ======================= launch ==============================
extern "C" void kernel_launch(void* const* d_in, const int* in_sizes, int n_in,
                              void* d_out, int out_size) {
    const float* x = (const float*)d_in[0];
    const float* y = (const float*)d_in[1];
    float* out = (float*)d_out;

    // Derive noise keys: nk1, nk2 = jax.random.split(jax.random.key(42))
    unsigned k1a, k1b, k2a, k2b;
#if JAX_PARTITIONABLE
    // fold-in split: nk_i = threefry((0,42), 0, i), both output words
    h_tf2x32(0u, 42u, 0u, 0u, k1a, k1b);   // nk1
    h_tf2x32(0u, 42u, 0u, 1u, k2a, k2b);   // nk2
#else
    // legacy split: counts [0,1,2,3] -> halves [0,1],[2,3]; lanes (0,2),(1,3)
    unsigned a0, b0, a1, b1;
    h_tf2x32(0u, 42u, 0u, 2u, a0, b0);
    h_tf2x32(0u, 42u, 1u, 3u, a1, b1);
    k1a = a0; k1b = a1;                     // nk1 = (word0 lane0, word0 lane1)
    k2a = b0; k2b = b1;                     // nk2 = (word1 lane0, word1 lane1)
#endif

    k_zero<<<(BATCH * BINS2 + 255) / 256, 256>>>();
    k_hist<<<BATCH * 16, 256>>>(x, y);
    k_fix<<<512, 128>>>(x, y, k1a, k1b, k2a, k2b);
    k_nmi<<<BATCH, BINS2>>>();
    k_fin<<<1, 32>>>(out);
}

// round 15
// speedup vs baseline: 2.2291x; 2.2291x over previous
#include <cuda_runtime.h>

// ======================= configuration =======================
#define NB        24
#define BINS2     576            // NB*NB
#define BATCH     64
#define LOCS      65536          // 256*256 downsampled locations per batch
#define NLOC      (BATCH * LOCS) // 4,194,304
#define HHALF     (NLOC / 2)     // 2,097,152 (legacy-mode pairing)
#define CAP       (1u << 21)     // worklist capacity (expected ~140K entries)
#define MARGIN_T  0.0074f        // max |bin-space shift| from noise = 12*5.45e-4 + ulp slack
#define FRAC_THR  (0.5f - MARGIN_T)

// JAX PRNG mode: 1 = partitionable — CONFIRMED by round-7 bench (rel_err 1.45e-5)
#define JAX_PARTITIONABLE 1

// ======================= device scratch ======================
__device__ unsigned g_hist[BATCH * BINS2];
__device__ unsigned g_wl[CAP];
__device__ unsigned g_wl_count;
__device__ float    g_nmi[BATCH];

// ======================= threefry2x32 ========================
__device__ __forceinline__ uint2 tf2x32(unsigned k0, unsigned k1, unsigned x0, unsigned x1) {
    const unsigned ks2 = k0 ^ k1 ^ 0x1BD11BDAu;
    x0 += k0; x1 += k1;
#define TF_RD(r) { x0 += x1; x1 = __funnelshift_l(x1, x1, (r)); x1 ^= x0; }
    TF_RD(13) TF_RD(15) TF_RD(26) TF_RD(6)   x0 += k1;  x1 += ks2 + 1u;
    TF_RD(17) TF_RD(29) TF_RD(16) TF_RD(24)  x0 += ks2; x1 += k0 + 2u;
    TF_RD(13) TF_RD(15) TF_RD(26) TF_RD(6)   x0 += k0;  x1 += k1 + 3u;
    TF_RD(17) TF_RD(29) TF_RD(16) TF_RD(24)  x0 += k1;  x1 += ks2 + 4u;
    TF_RD(13) TF_RD(15) TF_RD(26) TF_RD(6)   x0 += ks2; x1 += k0 + 5u;
#undef TF_RD
    return make_uint2(x0, x1);
}

static void h_tf2x32(unsigned k0, unsigned k1, unsigned x0, unsigned x1,
                     unsigned& o0, unsigned& o1) {
    const unsigned ks2 = k0 ^ k1 ^ 0x1BD11BDAu;
    x0 += k0; x1 += k1;
#define H_RD(r) { x0 += x1; x1 = (x1 << (r)) | (x1 >> (32 - (r))); x1 ^= x0; }
    H_RD(13) H_RD(15) H_RD(26) H_RD(6)   x0 += k1;  x1 += ks2 + 1u;
    H_RD(17) H_RD(29) H_RD(16) H_RD(24)  x0 += ks2; x1 += k0 + 2u;
    H_RD(13) H_RD(15) H_RD(26) H_RD(6)   x0 += k0;  x1 += k1 + 3u;
    H_RD(17) H_RD(29) H_RD(16) H_RD(24)  x0 += k1;  x1 += ks2 + 4u;
    H_RD(13) H_RD(15) H_RD(26) H_RD(6)   x0 += ks2; x1 += k0 + 5u;
#undef H_RD
    o0 = x0; o1 = x1;
}

// ============== noise-free bin + boundary flag ===============
__device__ __forceinline__ void binflag(float v, int& bin, bool& fl) {
    float t  = __fmaf_rn(v, 12.0f, 12.0f);
    int   bu = __float2int_rd(t);
    float fr = __fsub_rn(t, __int2float_rn(bu));         // frac in [0,1)
    fl  = fabsf(__fsub_rn(fr, 0.5f)) > FRAC_THR;         // within MARGIN_T of a boundary
    bin = min(max(bu, 0), NB - 1);
}

// ============== exact (JAX-faithful) noised bin ==============
__device__ __forceinline__ int noised_bin(float v, unsigned bits) {
    float f = __fsub_rn(__uint_as_float((bits >> 9) | 0x3f800000u), 1.0f);
    const float lo = -0.99999994f;                       // nextafterf(-1, 0)
    float u = fmaxf(__fmaf_rn(f, 2.0f, lo), lo);
    float nrm = __fmul_rn(1.41421356f, erfinvf(u));      // sqrt(2)*erfinv(u)
    float v2  = __fadd_rn(v, __fmul_rn(nrm, 0.0001f));   // xs + noise*1e-4
    float s   = __fmul_rn(__fadd_rn(v2, 1.0f), 0.5f);
    s = fminf(fmaxf(s, 0.001f), 0.999f);
    float t = __fmul_rn(s, 24.0f);
    int  b  = (int)floorf(t);
    return min(max(b, 0), NB - 1);
}

// ===================== kernel 0: zero =========================
__global__ void k_zero() {
    unsigned i = blockIdx.x * blockDim.x + threadIdx.x;
    if (i < BATCH * BINS2) g_hist[i] = 0u;
    if (i == 0) g_wl_count = 0u;
}

// ========== kernel 1: noise-free histogram + compact ==========
__global__ __launch_bounds__(256) void k_hist(const float* __restrict__ x,
                                              const float* __restrict__ y) {
    __shared__ unsigned sh[BINS2];
    const int b   = blockIdx.x >> 4;
    const int bb  = blockIdx.x & 15;
    const int tid = threadIdx.x;
    const int lane = tid & 31;
    const unsigned lmask = (1u << lane) - 1u;

    for (int i = tid; i < BINS2; i += 256) sh[i] = 0u;
    __syncthreads();

    const float* xb = x + ((size_t)b << 18);
    const float* yb = y + ((size_t)b << 18);

    for (int it = 0; it < 8; ++it) {
        int pp = (it << 8) + tid;
        int R  = (bb << 4) + (pp >> 7);
        int k  = pp & 127;
        size_t off = ((size_t)R << 10) + ((size_t)k << 2);
        const float4 xv = *reinterpret_cast<const float4*>(xb + off);
        const float4 yv = *reinterpret_cast<const float4*>(yb + off);

        int bx0, by0, bx1, by1; bool fx0, fy0, fx1, fy1;
        binflag(xv.x, bx0, fx0); binflag(yv.x, by0, fy0);
        binflag(xv.z, bx1, fx1); binflag(yv.z, by1, fy1);

        atomicAdd(&sh[bx0 * NB + by0], 1u);
        atomicAdd(&sh[bx1 * NB + by1], 1u);

        bool f0 = fx0 | fy0, f1 = fx1 | fy1;
        unsigned m0 = __ballot_sync(0xffffffffu, f0);
        unsigned m1 = __ballot_sync(0xffffffffu, f1);
        if (m0 | m1) {
            unsigned tot = (unsigned)(__popc(m0) + __popc(m1));
            unsigned base = 0;
            if (lane == 0) base = atomicAdd(&g_wl_count, tot);
            base = __shfl_sync(0xffffffffu, base, 0);
            unsigned j0 = ((unsigned)b << 16) | ((unsigned)R << 8) | ((unsigned)k << 1);
            if (f0) { unsigned s = base + __popc(m0 & lmask);               if (s < CAP) g_wl[s] = j0; }
            if (f1) { unsigned s = base + __popc(m0) + __popc(m1 & lmask);  if (s < CAP) g_wl[s] = j0 + 1u; }
        }
    }
    __syncthreads();
    unsigned* gh = g_hist + b * BINS2;
    for (int i = tid; i < BINS2; i += 256) {
        unsigned v = sh[i];
        if (v) atomicAdd(&gh[i], v);
    }
}

// ========== kernel 2: exact-noise corrections (worklist) ==========
__global__ __launch_bounds__(128) void k_fix(const float* __restrict__ x,
                                             const float* __restrict__ y,
                                             unsigned k1a, unsigned k1b,
                                             unsigned k2a, unsigned k2b) {
    unsigned n = g_wl_count; if (n > CAP) n = CAP;
    for (unsigned i = blockIdx.x * blockDim.x + threadIdx.x; i < n;
         i += gridDim.x * blockDim.x) {
        unsigned j   = g_wl[i];
        unsigned b   = j >> 16;
        unsigned R   = (j >> 8) & 255u;
        unsigned col = j & 255u;
        size_t src = ((size_t)b << 18) + ((size_t)R << 10) + ((size_t)col << 1);
        float xv = x[src], yv = y[src];

        int bxA, byA; bool d0, d1;
        binflag(xv, bxA, d0);
        binflag(yv, byA, d1);

#if JAX_PARTITIONABLE
        uint2 rx = tf2x32(k1a, k1b, 0u, j);
        uint2 ry = tf2x32(k2a, k2b, 0u, j);
        unsigned bxbits = rx.x ^ rx.y;
        unsigned bybits = ry.x ^ ry.y;
#else
        unsigned c0, c1; bool second;
        if (j < HHALF) { c0 = j;         c1 = j + HHALF; second = false; }
        else           { c0 = j - HHALF; c1 = j;         second = true;  }
        uint2 rx = tf2x32(k1a, k1b, c0, c1);
        uint2 ry = tf2x32(k2a, k2b, c0, c1);
        unsigned bxbits = second ? rx.y : rx.x;
        unsigned bybits = second ? ry.y : ry.x;
#endif
        int bxN = noised_bin(xv, bxbits);
        int byN = noised_bin(yv, bybits);

        int oldi = bxA * NB + byA;
        int newi = bxN * NB + byN;
        if (oldi != newi) {
            atomicAdd(&g_hist[b * BINS2 + oldi], 0xFFFFFFFFu);  // -1 (wraps)
            atomicAdd(&g_hist[b * BINS2 + newi], 1u);
        }
    }
}

// ================= kernel 3: per-batch NMI (all-f32, no FP64) ==========
// Round-7 ncu: the f64 version of this kernel was 67us (58% of total) — FP64
// log on sm_103a is a long software sequence and thread-0 ran 48 of them
// serially. Reference computes this epilogue in f32, so f32 here is *more*
// faithful as well as ~17x cheaper.
__global__ __launch_bounds__(BINS2) void k_nmi() {
    const int b = blockIdx.x, t = threadIdx.x;
    __shared__ float p[BINS2];
    __shared__ float xh[NB], yh[NB];
    __shared__ float wsum[BINS2 / 32];
    __shared__ float ent[2 * NB];

    p[t] = (float)g_hist[b * BINS2 + t] * (1.0f / 65536.0f);  // exact: /2^16
    __syncthreads();

    if (t < NB) {
        float s = 0.0f;
        for (int j = 0; j < NB; ++j) s += p[t * NB + j];
        xh[t] = s + 1e-5f;
    } else if (t < 2 * NB) {
        int c = t - NB;
        float s = 0.0f;
        for (int i = 0; i < NB; ++i) s += p[i * NB + c];
        yh[c] = s + 1e-5f;
    }
    __syncthreads();

    // joint MI term per thread (f32, MUFU-backed logf)
    float je   = p[t] + 1e-5f;
    float term = je * (logf(je) - logf(xh[t / NB] * yh[t % NB]));
    for (int o = 16; o; o >>= 1) term += __shfl_down_sync(0xffffffffu, term, o);
    if ((t & 31) == 0) wsum[t >> 5] = term;

    // marginal entropy terms, fully parallel (threads 0..47)
    if (t < 2 * NB) {
        float h = (t < NB) ? xh[t] : yh[t - NB];
        ent[t] = -h * logf(h);
    }
    __syncthreads();

    if (t == 0) {
        float mi = 0.0f;
        for (int w = 0; w < BINS2 / 32; ++w) mi += wsum[w];
        float hx = 0.0f, hy = 0.0f;
        for (int i = 0; i < NB; ++i) { hx += ent[i]; hy += ent[NB + i]; }
        float se  = hx + hy;
        float nmi = (se < 1e-10f) ? 0.0f : 2.0f * mi / se;
        g_nmi[b] = fminf(fmaxf(nmi, -1.0f), 1.0f);
    }
}

// ================= kernel 4: final reduce =====================
__global__ void k_fin(float* __restrict__ out) {
    if (threadIdx.x == 0) {
        float s = 0.0f;
        for (int i = 0; i < BATCH; ++i) s += g_nmi[i];
        float m = s * (1.0f / (float)BATCH);
        m = fminf(fmaxf(m, -1.0f), 1.0f);
        out[0] = -m;
    }
}

// ======================= launch ==============================
extern "C" void kernel_launch(void* const* d_in, const int* in_sizes, int n_in,
                              void* d_out, int out_size) {
    const float* x = (const float*)d_in[0];
    const float* y = (const float*)d_in[1];
    float* out = (float*)d_out;

    // Derive noise keys: nk1, nk2 = jax.random.split(jax.random.key(42))
    unsigned k1a, k1b, k2a, k2b;
#if JAX_PARTITIONABLE
    h_tf2x32(0u, 42u, 0u, 0u, k1a, k1b);   // nk1
    h_tf2x32(0u, 42u, 0u, 1u, k2a, k2b);   // nk2
#else
    unsigned a0, b0, a1, b1;
    h_tf2x32(0u, 42u, 0u, 2u, a0, b0);
    h_tf2x32(0u, 42u, 1u, 3u, a1, b1);
    k1a = a0; k1b = a1;
    k2a = b0; k2b = b1;
#endif

    k_zero<<<(BATCH * BINS2 + 255) / 256, 256>>>();
    k_hist<<<BATCH * 16, 256>>>(x, y);
    k_fix<<<512, 128>>>(x, y, k1a, k1b, k2a, k2b);
    k_nmi<<<BATCH, BINS2>>>();
    k_fin<<<1, 32>>>(out);
}